// round 9
// baseline (speedup 1.0000x reference)
#include <cuda_runtime.h>
#include <cstddef>

typedef unsigned long long ull;

// ---------------------------------------------------------------------------
// Packed f32x2 helpers (Blackwell sm_100+)
// ---------------------------------------------------------------------------
__device__ __forceinline__ ull bcast2(float a) {
    ull r; asm("mov.b64 %0, {%1, %1};" : "=l"(r) : "f"(a)); return r;
}
__device__ __forceinline__ void unpack2(ull v, float& a, float& b) {
    asm("mov.b64 {%0, %1}, %2;" : "=f"(a), "=f"(b) : "l"(v));
}
__device__ __forceinline__ ull fma2(ull a, ull b, ull c) {
    ull d; asm("fma.rn.f32x2 %0, %1, %2, %3;" : "=l"(d) : "l"(a), "l"(b), "l"(c));
    return d;
}
__device__ __forceinline__ float ex2_fast(float x) {
    float r; asm("ex2.approx.f32 %0, %1;" : "=f"(r) : "f"(x)); return r;
}
__device__ __forceinline__ float rcp_fast(float x) {
    float r; asm("rcp.approx.f32 %0, %1;" : "=f"(r) : "f"(x)); return r;
}
// accurate tanh: 1 - 2/(e^{2z}+1) from ex2/rcp (~1e-6 rel err)
__device__ __forceinline__ float tanh_acc(float z) {
    float e = ex2_fast(2.8853900817779268f * z);   // e^{2z}
    float r = rcp_fast(e + 1.0f);
    return fmaf(-2.0f, r, 1.0f);
}

// ---------------------------------------------------------------------------
// Single-net smem layout (floats), 2944 total:
//   [0)    W1half [64][16]   [1024) b1[16]
//   [1040) W2 [16][16]       [1296) b2[16]
//   [1312) W3 [16][16]       [1568) b3[16]
//   [1584) W4 [16][16]       [1840) b4[16]
//   [1856) W5half [16][64]   [2880) b5half[64]
// ---------------------------------------------------------------------------
#define TPB 128
#define R   4          // rows per thread (amortizes weight LDS over rows)
#define NET_FLOATS 2944

__device__ void load_net(float* L,
                         const float* W1, const float* b1,
                         const float* W2, const float* b2,
                         const float* W3, const float* b3,
                         const float* W4, const float* b4,
                         const float* W5, const float* b5,
                         int MOFF, int UOFF) {
    const int t = threadIdx.x;
    for (int idx = t; idx < 1024; idx += TPB) L[idx] = W1[(MOFF << 4) + idx];
    for (int idx = t; idx < 16;   idx += TPB) L[1024 + idx] = b1[idx];
    for (int idx = t; idx < 256;  idx += TPB) L[1040 + idx] = W2[idx];
    for (int idx = t; idx < 16;   idx += TPB) L[1296 + idx] = b2[idx];
    for (int idx = t; idx < 256;  idx += TPB) L[1312 + idx] = W3[idx];
    for (int idx = t; idx < 16;   idx += TPB) L[1568 + idx] = b3[idx];
    for (int idx = t; idx < 256;  idx += TPB) L[1584 + idx] = W4[idx];
    for (int idx = t; idx < 16;   idx += TPB) L[1840 + idx] = b4[idx];
    for (int idx = t; idx < 1024; idx += TPB)
        L[1856 + idx] = W5[(idx >> 6) * 128 + UOFF + (idx & 63)];
    for (int idx = t; idx < 64;   idx += TPB) L[2880 + idx] = b5[UOFF + idx];
}

// ---------------------------------------------------------------------------
// Hidden stack (layer1 64->16 + three 16->16 mids) for ONE net over R rows.
// x streamed from gmem/L2. Optionally copies the masked half to y (COPY).
// ---------------------------------------------------------------------------
template<bool COPY>
__device__ __forceinline__ void hidden_stack(const float* const (&xp)[R],
                                             float* const (&yp)[R],
                                             const bool (&ok)[R], int MOFF,
                                             const float* __restrict__ swn,
                                             float (&h)[R][16]) {
    // layer 1: 64 -> 16
    {
        const ulonglong2* W = (const ulonglong2*)swn;
        const ull* b = (const ull*)(swn + 1024);
        ull a[R][8];
        #pragma unroll
        for (int i = 0; i < R; i++)
            #pragma unroll
            for (int j = 0; j < 8; j++) a[i][j] = b[j];
        #pragma unroll 1
        for (int q = 0; q < 16; q++) {
            float4 xv[R];
            #pragma unroll
            for (int i = 0; i < R; i++) {
                xv[i] = *(const float4*)(xp[i] + MOFF + 4 * q);
                if (COPY && ok[i])
                    *(float4*)(yp[i] + MOFF + 4 * q) = xv[i];
            }
            #pragma unroll
            for (int kk = 0; kk < 4; kk++) {
                const int k = 4 * q + kk;
                ull xk[R];
                #pragma unroll
                for (int i = 0; i < R; i++)
                    xk[i] = bcast2(((const float*)&xv[i])[kk]);
                #pragma unroll
                for (int j = 0; j < 4; j++) {
                    ulonglong2 w = W[k * 4 + j];
                    #pragma unroll
                    for (int i = 0; i < R; i++) {
                        a[i][2 * j]     = fma2(xk[i], w.x, a[i][2 * j]);
                        a[i][2 * j + 1] = fma2(xk[i], w.y, a[i][2 * j + 1]);
                    }
                }
            }
        }
        #pragma unroll
        for (int i = 0; i < R; i++)
            #pragma unroll
            for (int j = 0; j < 8; j++) {
                float u, v; unpack2(a[i][j], u, v);
                h[i][2 * j]     = fmaxf(u, 0.0f);
                h[i][2 * j + 1] = fmaxf(v, 0.0f);
            }
    }
    // mids: 3x (16 -> 16)
    #pragma unroll 1
    for (int l = 0; l < 3; l++) {
        const ulonglong2* W = (const ulonglong2*)(swn + 1040 + l * 272);
        const ull* b = (const ull*)(swn + 1040 + l * 272 + 256);
        ull a[R][8];
        #pragma unroll
        for (int i = 0; i < R; i++)
            #pragma unroll
            for (int j = 0; j < 8; j++) a[i][j] = b[j];
        #pragma unroll
        for (int k = 0; k < 16; k++) {
            ull hk[R];
            #pragma unroll
            for (int i = 0; i < R; i++) hk[i] = bcast2(h[i][k]);
            #pragma unroll
            for (int j = 0; j < 4; j++) {
                ulonglong2 w = W[k * 4 + j];
                #pragma unroll
                for (int i = 0; i < R; i++) {
                    a[i][2 * j]     = fma2(hk[i], w.x, a[i][2 * j]);
                    a[i][2 * j + 1] = fma2(hk[i], w.y, a[i][2 * j + 1]);
                }
            }
        }
        #pragma unroll
        for (int i = 0; i < R; i++)
            #pragma unroll
            for (int j = 0; j < 8; j++) {
                float u, v; unpack2(a[i][j], u, v);
                h[i][2 * j]     = fmaxf(u, 0.0f);
                h[i][2 * j + 1] = fmaxf(v, 0.0f);
            }
    }
}

// Common preamble: row pointers for R rows.
#define ROW_SETUP                                                           \
    const int base = blockIdx.x * (TPB * R) + threadIdx.x;                  \
    const float* xp[R]; float* yp[R]; bool ok[R];                           \
    _Pragma("unroll")                                                       \
    for (int i = 0; i < R; i++) {                                           \
        int row = base + i * TPB;                                           \
        ok[i] = row < B;                                                    \
        int rc = ok[i] ? row : 0;                                           \
        xp[i] = x_in + (size_t)rc * 128;                                    \
        yp[i] = y    + (size_t)rc * 128;                                    \
    }

// ---------------------------------------------------------------------------
// t-kernel: y_u = x_u - t(x_m); (FIRST: also copy y_m = x_m)
// ---------------------------------------------------------------------------
template<int MOFF, bool FIRST>
__global__ void __launch_bounds__(TPB, 2)
t_kernel(const float* __restrict__ x_in,
         const float* __restrict__ W1, const float* __restrict__ b1,
         const float* __restrict__ W2, const float* __restrict__ b2,
         const float* __restrict__ W3, const float* __restrict__ b3,
         const float* __restrict__ W4, const float* __restrict__ b4,
         const float* __restrict__ W5, const float* __restrict__ b5,
         float* __restrict__ y, int B) {
    constexpr int UOFF = 64 - MOFF;
    __shared__ float sw[NET_FLOATS];
    load_net(sw, W1, b1, W2, b2, W3, b3, W4, b4, W5, b5, MOFF, UOFF);
    __syncthreads();

    ROW_SETUP;

    float h[R][16];
    hidden_stack<FIRST>(xp, yp, ok, MOFF, sw, h);

    // head: 4 chunks of 16 outputs; y_u = x_u - t
    const ulonglong2* W5s = (const ulonglong2*)(sw + 1856);
    const ull* b5s = (const ull*)(sw + 2880);
    #pragma unroll 1
    for (int c = 0; c < 4; c++) {
        ull o[R][8];
        #pragma unroll
        for (int i = 0; i < R; i++)
            #pragma unroll
            for (int u = 0; u < 8; u++) o[i][u] = b5s[c * 8 + u];
        #pragma unroll
        for (int k = 0; k < 16; k++) {
            ull hk[R];
            #pragma unroll
            for (int i = 0; i < R; i++) hk[i] = bcast2(h[i][k]);
            #pragma unroll
            for (int j = 0; j < 4; j++) {
                ulonglong2 w = W5s[k * 16 + c * 4 + j];
                #pragma unroll
                for (int i = 0; i < R; i++) {
                    o[i][2 * j]     = fma2(hk[i], w.x, o[i][2 * j]);
                    o[i][2 * j + 1] = fma2(hk[i], w.y, o[i][2 * j + 1]);
                }
            }
        }
        #pragma unroll
        for (int i = 0; i < R; i++) {
            if (!ok[i]) continue;
            #pragma unroll
            for (int q = 0; q < 4; q++) {
                float4 v = *(const float4*)(xp[i] + UOFF + c * 16 + 4 * q);
                float t0, t1, t2, t3;
                unpack2(o[i][2 * q],     t0, t1);
                unpack2(o[i][2 * q + 1], t2, t3);
                *(float4*)(yp[i] + UOFF + c * 16 + 4 * q) =
                    make_float4(v.x - t0, v.y - t1, v.z - t2, v.w - t3);
            }
        }
    }
}

// ---------------------------------------------------------------------------
// s-kernel: s = tanh(net_s(y_m)); y_u *= exp(-s); ld -= sum(s)
// ---------------------------------------------------------------------------
template<int MOFF, bool FIRST>
__global__ void __launch_bounds__(TPB, 2)
s_kernel(const float* __restrict__ x_in,
         const float* __restrict__ W1, const float* __restrict__ b1,
         const float* __restrict__ W2, const float* __restrict__ b2,
         const float* __restrict__ W3, const float* __restrict__ b3,
         const float* __restrict__ W4, const float* __restrict__ b4,
         const float* __restrict__ W5, const float* __restrict__ b5,
         float* __restrict__ y, float* __restrict__ ld_out, int B) {
    constexpr int UOFF = 64 - MOFF;
    __shared__ float sw[NET_FLOATS];
    load_net(sw, W1, b1, W2, b2, W3, b3, W4, b4, W5, b5, MOFF, UOFF);
    __syncthreads();

    ROW_SETUP;

    float h[R][16];
    hidden_stack<false>(xp, yp, ok, MOFF, sw, h);

    const ulonglong2* W5s = (const ulonglong2*)(sw + 1856);
    const ull* b5s = (const ull*)(sw + 2880);
    float ldsum[R];
    #pragma unroll
    for (int i = 0; i < R; i++) ldsum[i] = 0.0f;

    #pragma unroll 1
    for (int c = 0; c < 4; c++) {
        ull o[R][8];
        #pragma unroll
        for (int i = 0; i < R; i++)
            #pragma unroll
            for (int u = 0; u < 8; u++) o[i][u] = b5s[c * 8 + u];
        #pragma unroll
        for (int k = 0; k < 16; k++) {
            ull hk[R];
            #pragma unroll
            for (int i = 0; i < R; i++) hk[i] = bcast2(h[i][k]);
            #pragma unroll
            for (int j = 0; j < 4; j++) {
                ulonglong2 w = W5s[k * 16 + c * 4 + j];
                #pragma unroll
                for (int i = 0; i < R; i++) {
                    o[i][2 * j]     = fma2(hk[i], w.x, o[i][2 * j]);
                    o[i][2 * j + 1] = fma2(hk[i], w.y, o[i][2 * j + 1]);
                }
            }
        }
        #pragma unroll
        for (int i = 0; i < R; i++) {
            #pragma unroll
            for (int q = 0; q < 2; q++) {
                float4 v0 = *(const float4*)(xp[i] + UOFF + c * 16 + 8 * q);
                float4 v1 = *(const float4*)(xp[i] + UOFF + c * 16 + 8 * q + 4);
                float z[8], s[8];
                unpack2(o[i][4 * q],     z[0], z[1]);
                unpack2(o[i][4 * q + 1], z[2], z[3]);
                unpack2(o[i][4 * q + 2], z[4], z[5]);
                unpack2(o[i][4 * q + 3], z[6], z[7]);
                #pragma unroll
                for (int u = 0; u < 8; u++) {
                    s[u] = tanh_acc(z[u]);
                    ldsum[i] += s[u];
                }
                float4 r0 = make_float4(
                    v0.x * ex2_fast(-1.4426950408889634f * s[0]),
                    v0.y * ex2_fast(-1.4426950408889634f * s[1]),
                    v0.z * ex2_fast(-1.4426950408889634f * s[2]),
                    v0.w * ex2_fast(-1.4426950408889634f * s[3]));
                float4 r1 = make_float4(
                    v1.x * ex2_fast(-1.4426950408889634f * s[4]),
                    v1.y * ex2_fast(-1.4426950408889634f * s[5]),
                    v1.z * ex2_fast(-1.4426950408889634f * s[6]),
                    v1.w * ex2_fast(-1.4426950408889634f * s[7]));
                if (ok[i]) {
                    *(float4*)(yp[i] + UOFF + c * 16 + 8 * q)     = r0;
                    *(float4*)(yp[i] + UOFF + c * 16 + 8 * q + 4) = r1;
                }
            }
        }
    }

    #pragma unroll
    for (int i = 0; i < R; i++) {
        int row = base + i * TPB;
        if (ok[i])
            ld_out[row] = (FIRST ? 0.0f : ld_out[row]) - ldsum[i];
    }
}

// ---------------------------------------------------------------------------
// Harness entry: 12 sequential launches (t then s per coupling layer).
// Input order: x, masks, tW1,tb1,...,tW5,tb5, sW1,sb1,...,sW5,sb5
// Output: y [B,128] then logdet [B]
// ---------------------------------------------------------------------------
extern "C" void kernel_launch(void* const* d_in, const int* in_sizes, int n_in,
                              void* d_out, int out_size) {
    const float* x = (const float*)d_in[0];
    const float* P[20];
    for (int i = 0; i < 20; i++) P[i] = (const float*)d_in[2 + i];

    const int B = in_sizes[0] / 128;
    float* y  = (float*)d_out;
    float* ld = y + (size_t)B * 128;

    const int ROWS_PER_BLOCK = TPB * R;
    const dim3 grid((B + ROWS_PER_BLOCK - 1) / ROWS_PER_BLOCK), block(TPB);

    // Processed layer i uses original layer p = 5 - i.
    // i even: masked half [0,64) (MOFF=0); i odd: MOFF=64.
#define TARGS(p)                                                             \
    P[0] + (p) * 2048, P[1] + (p) * 16,  P[2] + (p) * 256, P[3] + (p) * 16,  \
    P[4] + (p) * 256,  P[5] + (p) * 16,  P[6] + (p) * 256, P[7] + (p) * 16,  \
    P[8] + (p) * 2048, P[9] + (p) * 128
#define SARGS(p)                                                             \
    P[10] + (p) * 2048, P[11] + (p) * 16, P[12] + (p) * 256, P[13] + (p) * 16,\
    P[14] + (p) * 256,  P[15] + (p) * 16, P[16] + (p) * 256, P[17] + (p) * 16,\
    P[18] + (p) * 2048, P[19] + (p) * 128

    t_kernel<0,  true ><<<grid, block>>>(x, TARGS(5), y, B);
    s_kernel<0,  true ><<<grid, block>>>(y, SARGS(5), y, ld, B);
    t_kernel<64, false><<<grid, block>>>(y, TARGS(4), y, B);
    s_kernel<64, false><<<grid, block>>>(y, SARGS(4), y, ld, B);
    t_kernel<0,  false><<<grid, block>>>(y, TARGS(3), y, B);
    s_kernel<0,  false><<<grid, block>>>(y, SARGS(3), y, ld, B);
    t_kernel<64, false><<<grid, block>>>(y, TARGS(2), y, B);
    s_kernel<64, false><<<grid, block>>>(y, SARGS(2), y, ld, B);
    t_kernel<0,  false><<<grid, block>>>(y, TARGS(1), y, B);
    s_kernel<0,  false><<<grid, block>>>(y, SARGS(1), y, ld, B);
    t_kernel<64, false><<<grid, block>>>(y, TARGS(0), y, B);
    s_kernel<64, false><<<grid, block>>>(y, SARGS(0), y, ld, B);
#undef TARGS
#undef SARGS
}